// round 2
// baseline (speedup 1.0000x reference)
#include <cuda_runtime.h>

#define NP 262144          // 512*512 pixels
#define HDIM 96
#define QKVC 288

// Scratch (allowed: __device__ globals, no runtime allocation)
__device__ float g_qkv[(size_t)QKVC * NP];   // 302 MB: qkv after 1x1 conv (pre-depthwise)
__device__ float g_mid[(size_t)HDIM * NP];   // 100 MB: attention output, pre-proj

// ---------------------------------------------------------------------------
// SGEMM: C[o][p] = sum_i A[o][i] * B[i][p] + bias[o]
// K = 96 (two BK=48 tiles), BM = 96, BN = 128, 256 threads, 6x8 micro-tile.
// ---------------------------------------------------------------------------
__device__ __forceinline__ void gemm_body(const float* __restrict__ A,
                                          const float* __restrict__ bias,
                                          const float* __restrict__ B,
                                          float* __restrict__ C) {
    __shared__ __align__(16) float As[48][96];
    __shared__ __align__(16) float Bs[48][128];

    const int t  = threadIdx.x;
    const int tx = t & 15;       // 16 column groups
    const int ty = t >> 4;       // 16 row groups
    const int o0 = blockIdx.y * 96;
    const size_t p0 = (size_t)blockIdx.x * 128;

    float acc[6][8];
#pragma unroll
    for (int m = 0; m < 6; m++) {
        float bv = bias[o0 + ty * 6 + m];
#pragma unroll
        for (int n = 0; n < 8; n++) acc[m][n] = bv;
    }

    for (int kt = 0; kt < 2; kt++) {
        // A tile: As[k][o] = A[(o0+o)*96 + kt*48 + k]   (coalesced on k)
        for (int idx = t; idx < 48 * 96; idx += 256) {
            int o = idx / 48, k = idx % 48;
            As[k][o] = A[(o0 + o) * 96 + kt * 48 + k];
        }
        // B tile (float4)
        for (int idx = t; idx < 48 * 32; idx += 256) {
            int k = idx >> 5, c4 = idx & 31;
            *(float4*)&Bs[k][c4 * 4] =
                *(const float4*)(B + (size_t)(kt * 48 + k) * NP + p0 + c4 * 4);
        }
        __syncthreads();

#pragma unroll 4
        for (int k = 0; k < 48; k++) {
            float a[6];
#pragma unroll
            for (int m = 0; m < 6; m++) a[m] = As[k][ty * 6 + m];
            float4 b0 = *(float4*)&Bs[k][tx * 4];
            float4 b1 = *(float4*)&Bs[k][64 + tx * 4];
            float bb[8] = {b0.x, b0.y, b0.z, b0.w, b1.x, b1.y, b1.z, b1.w};
#pragma unroll
            for (int m = 0; m < 6; m++)
#pragma unroll
                for (int n = 0; n < 8; n++) acc[m][n] += a[m] * bb[n];
        }
        __syncthreads();
    }

#pragma unroll
    for (int m = 0; m < 6; m++) {
        float* cp = C + (size_t)(o0 + ty * 6 + m) * NP + p0;
        *(float4*)(cp + tx * 4)      = make_float4(acc[m][0], acc[m][1], acc[m][2], acc[m][3]);
        *(float4*)(cp + 64 + tx * 4) = make_float4(acc[m][4], acc[m][5], acc[m][6], acc[m][7]);
    }
}

__global__ __launch_bounds__(256) void k_gemm_qkv(const float* __restrict__ W,
                                                  const float* __restrict__ b,
                                                  const float* __restrict__ x) {
    gemm_body(W, b, x, g_qkv);
}

__global__ __launch_bounds__(256) void k_gemm_proj(const float* __restrict__ W,
                                                   const float* __restrict__ b,
                                                   float* __restrict__ out) {
    gemm_body(W, b, g_mid, out);
}

// ---------------------------------------------------------------------------
// Per (window, head) kernel: depthwise 3x3 (SAME within 8x8 window),
// L2-normalize q/k over spatial axis, channel attn (16x16, *temperature),
// spatial attn (64x64 + relative position bias), softmax both,
// out = attn_ch @ v @ attn_sp  ->  g_mid.
// grid = (4096 windows, 6 heads), 128 threads.
// ---------------------------------------------------------------------------
__global__ __launch_bounds__(128) void window_attn(const float* __restrict__ dw_w,
                                                   const float* __restrict__ dw_b,
                                                   const float* __restrict__ temperature,
                                                   const float* __restrict__ bias_table) {
    __shared__ __align__(16) float raw[48][64];   // qkv before depthwise
    __shared__ __align__(16) float cv[48][64];    // after depthwise; rows 0-15 q, 16-31 k, 32-47 v
    __shared__ __align__(16) float asp[64][64];   // spatial attention
    __shared__ __align__(16) float tmp[16][64];   // attn_ch @ v
    __shared__ float ach[16][16];                 // channel attention
    __shared__ float dww[48][9];
    __shared__ float dwb[48];
    __shared__ float btab[225];

    const int t   = threadIdx.x;
    const int win = blockIdx.x;
    const int h   = blockIdx.y;
    const int wy  = win >> 6, wx = win & 63;
    const size_t base = (size_t)(wy * 8) * 512 + (size_t)wx * 8;

    // ---- load raw qkv window (48 channels x 64 px), float4 ----
    for (int i = t; i < 768; i += 128) {
        int cl = i >> 4;
        int r  = i & 15;
        int dy = r >> 1, half = r & 1;
        int gch = (cl >> 4) * 96 + h * 16 + (cl & 15);
        *(float4*)&raw[cl][dy * 8 + half * 4] =
            *(const float4*)(g_qkv + (size_t)gch * NP + base + dy * 512 + half * 4);
    }
    // ---- depthwise weights / bias / bias table column ----
    for (int i = t; i < 432; i += 128) {
        int cl = i / 9, j = i % 9;
        int gch = (cl >> 4) * 96 + h * 16 + (cl & 15);
        dww[cl][j] = dw_w[gch * 9 + j];
    }
    if (t < 48) {
        int gch = (t >> 4) * 96 + h * 16 + (t & 15);
        dwb[t] = dw_b[gch];
    }
    for (int i = t; i < 225; i += 128) btab[i] = bias_table[i * 6 + h];
    __syncthreads();

    // ---- depthwise 3x3, zero padding at window border ----
    for (int i = t; i < 3072; i += 128) {
        int cl = i >> 6, pos = i & 63;
        int dy = pos >> 3, dx = pos & 7;
        float acc = dwb[cl];
#pragma unroll
        for (int ky = 0; ky < 3; ky++) {
            int yy = dy + ky - 1;
            if (yy < 0 || yy >= 8) continue;
#pragma unroll
            for (int kx = 0; kx < 3; kx++) {
                int xx = dx + kx - 1;
                if (xx < 0 || xx >= 8) continue;
                acc += dww[cl][ky * 3 + kx] * raw[cl][yy * 8 + xx];
            }
        }
        cv[cl][pos] = acc;
    }
    __syncthreads();

    // ---- L2-normalize q rows (0-15) and k rows (16-31) in place ----
    // (the hd^-0.5 scale on q cancels under normalization)
    {
        int r  = t >> 2;             // 0..31
        int qo = (t & 3) * 16;
        int rot = t >> 2;
        float s = 0.f;
#pragma unroll
        for (int i = 0; i < 16; i++) {
            float v = cv[r][qo + ((i + rot) & 15)];
            s += v * v;
        }
        s += __shfl_xor_sync(0xffffffffu, s, 1);
        s += __shfl_xor_sync(0xffffffffu, s, 2);
        float nf = 1.0f / fmaxf(sqrtf(s), 1e-12f);
#pragma unroll
        for (int i = 0; i < 16; i++) cv[r][qo + ((i + rot) & 15)] *= nf;
    }
    __syncthreads();

    const float tempv = temperature[h];

    // ---- channel attention: ach[c][d] = (qn_c . kn_d) * temperature ----
    for (int i = t; i < 256; i += 128) {
        int c = i >> 4, d = i & 15;
        float s = 0.f;
#pragma unroll
        for (int n4 = 0; n4 < 16; n4++) {
            float4 q4 = *(float4*)&cv[c][n4 * 4];
            float4 k4 = *(float4*)&cv[16 + d][n4 * 4];
            s += q4.x * k4.x + q4.y * k4.y + q4.z * k4.z + q4.w * k4.w;
        }
        ach[c][d] = s * tempv;
    }

    // ---- spatial attention: asp[n][m] = sum_c qn[c][n]*kn[c][m] + bias ----
    {
        int m  = t & 63;
        int n0 = t >> 6;
        float kb[16];
#pragma unroll
        for (int c = 0; c < 16; c++) kb[c] = cv[16 + c][m];
#pragma unroll 4
        for (int j = 0; j < 32; j++) {
            int n = n0 + 2 * j;
            float s = 0.f;
#pragma unroll
            for (int c = 0; c < 16; c++) s += cv[c][n] * kb[c];
            int rp = ((n >> 3) - (m >> 3) + 7) * 15 + ((n & 7) - (m & 7) + 7);
            asp[n][m] = s + btab[rp];
        }
    }
    __syncthreads();

    // ---- softmax: asp rows (all 128 threads, 2 per row) + ach rows (t<32) ----
    {
        int r   = t >> 1;
        int off = (t & 1) * 32;
        int rot = t >> 1;
        float mx = -1e30f;
#pragma unroll
        for (int i = 0; i < 32; i++) mx = fmaxf(mx, asp[r][off + ((i + rot) & 31)]);
        mx = fmaxf(mx, __shfl_xor_sync(0xffffffffu, mx, 1));
        float sum = 0.f;
#pragma unroll
        for (int i = 0; i < 32; i++) {
            int j = off + ((i + rot) & 31);
            float e = __expf(asp[r][j] - mx);
            asp[r][j] = e;
            sum += e;
        }
        sum += __shfl_xor_sync(0xffffffffu, sum, 1);
        float inv = 1.0f / sum;
#pragma unroll
        for (int i = 0; i < 32; i++) asp[r][off + ((i + rot) & 31)] *= inv;
    }
    if (t < 32) {
        int r = t >> 1, off = (t & 1) * 8;
        float mx = -1e30f;
#pragma unroll
        for (int i = 0; i < 8; i++) mx = fmaxf(mx, ach[r][off + i]);
        mx = fmaxf(mx, __shfl_xor_sync(0xffffffffu, mx, 1));
        float sum = 0.f;
#pragma unroll
        for (int i = 0; i < 8; i++) {
            float e = __expf(ach[r][off + i] - mx);
            ach[r][off + i] = e;
            sum += e;
        }
        sum += __shfl_xor_sync(0xffffffffu, sum, 1);
        float inv = 1.0f / sum;
#pragma unroll
        for (int i = 0; i < 8; i++) ach[r][off + i] *= inv;
    }
    __syncthreads();

    // ---- tmp = ach @ v : tmp[c][n] ----
    {
        int c  = t >> 3;           // 0..15
        int nb = (t & 7) * 8;      // 8 consecutive n
        float acc[8] = {0, 0, 0, 0, 0, 0, 0, 0};
#pragma unroll
        for (int d = 0; d < 16; d++) {
            float a = ach[c][d];
            float4 v0 = *(float4*)&cv[32 + d][nb];
            float4 v1 = *(float4*)&cv[32 + d][nb + 4];
            acc[0] += a * v0.x; acc[1] += a * v0.y; acc[2] += a * v0.z; acc[3] += a * v0.w;
            acc[4] += a * v1.x; acc[5] += a * v1.y; acc[6] += a * v1.z; acc[7] += a * v1.w;
        }
        *(float4*)&tmp[c][nb]     = make_float4(acc[0], acc[1], acc[2], acc[3]);
        *(float4*)&tmp[c][nb + 4] = make_float4(acc[4], acc[5], acc[6], acc[7]);
    }
    __syncthreads();

    // ---- out[c][m] = sum_n tmp[c][n] * asp[n][m] ; write to g_mid ----
    {
        int c  = t >> 3;           // 0..15
        int mb = (t & 7) * 8;      // 8 consecutive m -> one window row (dy = t&7)
        float acc[8] = {0, 0, 0, 0, 0, 0, 0, 0};
#pragma unroll 8
        for (int n = 0; n < 64; n++) {
            float a = tmp[c][n];
            float4 v0 = *(float4*)&asp[n][mb];
            float4 v1 = *(float4*)&asp[n][mb + 4];
            acc[0] += a * v0.x; acc[1] += a * v0.y; acc[2] += a * v0.z; acc[3] += a * v0.w;
            acc[4] += a * v1.x; acc[5] += a * v1.y; acc[6] += a * v1.z; acc[7] += a * v1.w;
        }
        int dy = t & 7;
        float* op = g_mid + (size_t)(h * 16 + c) * NP + base + (size_t)dy * 512;
        *(float4*)(op)     = make_float4(acc[0], acc[1], acc[2], acc[3]);
        *(float4*)(op + 4) = make_float4(acc[4], acc[5], acc[6], acc[7]);
    }
}

// ---------------------------------------------------------------------------
extern "C" void kernel_launch(void* const* d_in, const int* in_sizes, int n_in,
                              void* d_out, int out_size) {
    const float* x      = (const float*)d_in[0];
    const float* qkv_w  = (const float*)d_in[1];
    const float* qkv_b  = (const float*)d_in[2];
    const float* dw_w   = (const float*)d_in[3];
    const float* dw_b   = (const float*)d_in[4];
    const float* proj_w = (const float*)d_in[5];
    const float* proj_b = (const float*)d_in[6];
    const float* temp   = (const float*)d_in[7];
    const float* btab   = (const float*)d_in[8];
    float* out = (float*)d_out;

    dim3 g1(2048, 3);
    k_gemm_qkv<<<g1, 256>>>(qkv_w, qkv_b, x);

    dim3 g2(4096, 6);
    window_attn<<<g2, 128>>>(dw_w, dw_b, temp, btab);

    dim3 g3(2048, 1);
    k_gemm_proj<<<g3, 256>>>(proj_w, proj_b, out);
}

// round 5
// speedup vs baseline: 1.2870x; 1.2870x over previous
#include <cuda_runtime.h>

#define NP 262144          // 512*512 pixels
#define HDIM 96

// Scratch (allowed: __device__ globals)
__device__ float g_mid[(size_t)HDIM * NP];   // attention output, pre-proj

// ---------------------------------------------------------------------------
// Proj SGEMM: C[o][p] = sum_i A[o][i] * g_mid[i][p] + bias[o]
// K = 96, BM = 96, BN = 128, 256 threads, 6x8 micro-tile.
// ---------------------------------------------------------------------------
__global__ __launch_bounds__(256) void k_gemm_proj(const float* __restrict__ A,
                                                   const float* __restrict__ bias,
                                                   float* __restrict__ C) {
    __shared__ __align__(16) float As[48][96];
    __shared__ __align__(16) float Bs[48][128];

    const int t  = threadIdx.x;
    const int tx = t & 15;
    const int ty = t >> 4;
    const size_t p0 = (size_t)blockIdx.x * 128;
    const float* __restrict__ B = g_mid;

    float acc[6][8];
#pragma unroll
    for (int m = 0; m < 6; m++) {
        float bv = bias[ty * 6 + m];
#pragma unroll
        for (int n = 0; n < 8; n++) acc[m][n] = bv;
    }

    for (int kt = 0; kt < 2; kt++) {
        for (int idx = t; idx < 48 * 96; idx += 256) {
            int o = idx / 48, k = idx % 48;
            As[k][o] = A[o * 96 + kt * 48 + k];
        }
        for (int idx = t; idx < 48 * 32; idx += 256) {
            int k = idx >> 5, c4 = idx & 31;
            *(float4*)&Bs[k][c4 * 4] =
                *(const float4*)(B + (size_t)(kt * 48 + k) * NP + p0 + c4 * 4);
        }
        __syncthreads();

#pragma unroll 4
        for (int k = 0; k < 48; k++) {
            float a[6];
#pragma unroll
            for (int m = 0; m < 6; m++) a[m] = As[k][ty * 6 + m];
            float4 b0 = *(float4*)&Bs[k][tx * 4];
            float4 b1 = *(float4*)&Bs[k][64 + tx * 4];
            float bb[8] = {b0.x, b0.y, b0.z, b0.w, b1.x, b1.y, b1.z, b1.w};
#pragma unroll
            for (int m = 0; m < 6; m++)
#pragma unroll
                for (int n = 0; n < 8; n++) acc[m][n] += a[m] * bb[n];
        }
        __syncthreads();
    }

#pragma unroll
    for (int m = 0; m < 6; m++) {
        float* cp = C + (size_t)(ty * 6 + m) * NP + p0;
        *(float4*)(cp + tx * 4)      = make_float4(acc[m][0], acc[m][1], acc[m][2], acc[m][3]);
        *(float4*)(cp + 64 + tx * 4) = make_float4(acc[m][4], acc[m][5], acc[m][6], acc[m][7]);
    }
}

// ---------------------------------------------------------------------------
// Fused per-(head, window) kernel, 256 threads:
//   qkv 1x1 GEMM (48x96 . 96x64) -> depthwise 3x3 (SAME in window) ->
//   L2-normalize q/k over spatial -> channel attn (16x16, *temp) +
//   spatial attn (64x64 + rel bias) -> softmax -> attn_ch @ v @ attn_sp
// Dynamic smem 71424 B, unioned regions. grid = (6 heads, 4096 windows).
// ---------------------------------------------------------------------------
// smem offsets (floats)
#define OFF_XS   0        // [96][64]             (dead after GEMM)
#define OFF_W    6144     // [48][97]             (dead after GEMM)
#define OFF_ASP  0        // [64][64]   overlays XS
#define OFF_TMP  4096     // [16][64]   overlays XS
#define OFF_ACH  5120     // [16][17]   overlays XS tail
#define OFF_RAW  10800    // [48][64]
#define OFF_CV   13872    // [48][68]   (padded stride 68)
#define OFF_DWW  17136    // [48][9]
#define OFF_DWB  17568    // [48]
#define OFF_BT   17616    // [225]
#define SMEM_FLOATS 17856
#define SMEM_BYTES  (SMEM_FLOATS * 4)

__global__ __launch_bounds__(256) void window_attn_fused(
        const float* __restrict__ x,
        const float* __restrict__ qkv_w,
        const float* __restrict__ qkv_b,
        const float* __restrict__ dw_w,
        const float* __restrict__ dw_b,
        const float* __restrict__ temperature,
        const float* __restrict__ bias_table) {
    extern __shared__ __align__(16) float sm[];
    float* XS  = sm + OFF_XS;
    float* Wt  = sm + OFF_W;
    float* ASP = sm + OFF_ASP;
    float* TMP = sm + OFF_TMP;
    float* ACH = sm + OFF_ACH;
    float* RAW = sm + OFF_RAW;
    float* CV  = sm + OFF_CV;
    float* DWW = sm + OFF_DWW;
    float* DWB = sm + OFF_DWB;
    float* BT  = sm + OFF_BT;

    const int t   = threadIdx.x;
    const int h   = blockIdx.x;      // 0..5
    const int win = blockIdx.y;      // 0..4095
    const int wy  = win >> 6, wx = win & 63;
    const size_t base = (size_t)(wy * 8) * 512 + (size_t)wx * 8;

    // ---- phase 0: loads ----
    // x window: 96 channels x 64 px (float4)
    for (int i = t; i < 1536; i += 256) {
        int ch = i >> 4, r = i & 15;
        int dy = r >> 1, half = r & 1;
        *(float4*)&XS[ch * 64 + dy * 8 + half * 4] =
            *(const float4*)(x + (size_t)ch * NP + base + (size_t)dy * 512 + half * 4);
    }
    // qkv weights for this head's 48 output channels (padded stride 97)
    for (int i = t; i < 1152; i += 256) {
        int row = i / 24, c4 = i % 24;
        int gch = (row >> 4) * 96 + h * 16 + (row & 15);
        float4 wv = *(const float4*)(qkv_w + gch * 96 + c4 * 4);
        float* d = &Wt[row * 97 + c4 * 4];
        d[0] = wv.x; d[1] = wv.y; d[2] = wv.z; d[3] = wv.w;
    }
    // depthwise weights / bias / bias table column
    for (int i = t; i < 432; i += 256) {
        int cl = i / 9, j = i % 9;
        int gch = (cl >> 4) * 96 + h * 16 + (cl & 15);
        DWW[cl * 9 + j] = dw_w[gch * 9 + j];
    }
    if (t < 48) {
        int gch = (t >> 4) * 96 + h * 16 + (t & 15);
        DWB[t] = dw_b[gch];
    }
    // FIX: full coverage of the 225-entry bias table (previous conditional
    // left BT[208..224] uninitialized -> rel_err 2.2e-2)
    for (int i = t; i < 225; i += 256) BT[i] = bias_table[i * 6 + h];
    __syncthreads();

    // ---- phase 1: qkv GEMM -> RAW[48][64] (+bias) ----
    {
        const int r0 = t >> 4;       // 0..15
        const int tx = t & 15;       // 4 cols each
        float a0r[4], a1r[4], a2r[4];
        float b0 = qkv_b[0 * 96 + h * 16 + r0];
        float b1 = qkv_b[1 * 96 + h * 16 + r0];
        float b2 = qkv_b[2 * 96 + h * 16 + r0];
#pragma unroll
        for (int j = 0; j < 4; j++) { a0r[j] = b0; a1r[j] = b1; a2r[j] = b2; }
#pragma unroll 4
        for (int k = 0; k < 96; k++) {
            float4 bx = *(float4*)&XS[k * 64 + tx * 4];
            float a0 = Wt[r0 * 97 + k];
            float a1 = Wt[(r0 + 16) * 97 + k];
            float a2 = Wt[(r0 + 32) * 97 + k];
            a0r[0] += a0 * bx.x; a0r[1] += a0 * bx.y; a0r[2] += a0 * bx.z; a0r[3] += a0 * bx.w;
            a1r[0] += a1 * bx.x; a1r[1] += a1 * bx.y; a1r[2] += a1 * bx.z; a1r[3] += a1 * bx.w;
            a2r[0] += a2 * bx.x; a2r[1] += a2 * bx.y; a2r[2] += a2 * bx.z; a2r[3] += a2 * bx.w;
        }
        *(float4*)&RAW[r0 * 64 + tx * 4]        = make_float4(a0r[0], a0r[1], a0r[2], a0r[3]);
        *(float4*)&RAW[(r0 + 16) * 64 + tx * 4] = make_float4(a1r[0], a1r[1], a1r[2], a1r[3]);
        *(float4*)&RAW[(r0 + 32) * 64 + tx * 4] = make_float4(a2r[0], a2r[1], a2r[2], a2r[3]);
    }
    __syncthreads();

    // ---- phase 2: depthwise 3x3 (zero pad at window border) -> CV ----
    for (int i = t; i < 3072; i += 256) {
        int cl = i >> 6, pos = i & 63;
        int dy = pos >> 3, dx = pos & 7;
        float acc = DWB[cl];
#pragma unroll
        for (int ky = 0; ky < 3; ky++) {
            int yy = dy + ky - 1;
            if (yy < 0 || yy >= 8) continue;
#pragma unroll
            for (int kx = 0; kx < 3; kx++) {
                int xx = dx + kx - 1;
                if (xx < 0 || xx >= 8) continue;
                acc += DWW[cl * 9 + ky * 3 + kx] * RAW[cl * 64 + yy * 8 + xx];
            }
        }
        CV[cl * 68 + pos] = acc;
    }
    __syncthreads();

    // ---- phase 3: L2-normalize q rows (0-15) and k rows (16-31) over N=64 ----
    {
        int r  = t >> 3;             // 0..31
        int l8 = t & 7;              // 8 elems each
        float* rp = &CV[r * 68 + l8 * 8];
        float4 v0 = *(float4*)rp;
        float4 v1 = *(float4*)(rp + 4);
        float s = v0.x*v0.x + v0.y*v0.y + v0.z*v0.z + v0.w*v0.w
                + v1.x*v1.x + v1.y*v1.y + v1.z*v1.z + v1.w*v1.w;
        s += __shfl_xor_sync(0xffffffffu, s, 1);
        s += __shfl_xor_sync(0xffffffffu, s, 2);
        s += __shfl_xor_sync(0xffffffffu, s, 4);
        float nf = 1.0f / fmaxf(sqrtf(s), 1e-12f);
        v0.x *= nf; v0.y *= nf; v0.z *= nf; v0.w *= nf;
        v1.x *= nf; v1.y *= nf; v1.z *= nf; v1.w *= nf;
        *(float4*)rp       = v0;
        *(float4*)(rp + 4) = v1;
    }
    __syncthreads();

    const float tempv = temperature[h];

    // ---- phase 4: channel attention logits ACH[c][d] (stride 17) ----
    {
        int c = t >> 4, d = t & 15;
        float s = 0.f;
#pragma unroll
        for (int n4 = 0; n4 < 16; n4++) {
            float4 q4 = *(float4*)&CV[c * 68 + n4 * 4];
            float4 k4 = *(float4*)&CV[(16 + d) * 68 + n4 * 4];
            s += q4.x * k4.x + q4.y * k4.y + q4.z * k4.z + q4.w * k4.w;
        }
        ACH[c * 17 + d] = s * tempv;
    }

    // ---- phase 5: spatial attention logits + rel bias -> ASP[n][m] ----
    {
        int m  = t & 63;
        int ng = t >> 6;             // n block of 16
        float kb[16];
#pragma unroll
        for (int c = 0; c < 16; c++) kb[c] = CV[(16 + c) * 68 + m];
        float acc[16];
#pragma unroll
        for (int j = 0; j < 16; j++) acc[j] = 0.f;
#pragma unroll
        for (int c = 0; c < 16; c++) {
            float kv = kb[c];
            float4 q0 = *(float4*)&CV[c * 68 + ng * 16];
            float4 q1 = *(float4*)&CV[c * 68 + ng * 16 + 4];
            float4 q2 = *(float4*)&CV[c * 68 + ng * 16 + 8];
            float4 q3 = *(float4*)&CV[c * 68 + ng * 16 + 12];
            acc[0]  += q0.x * kv; acc[1]  += q0.y * kv; acc[2]  += q0.z * kv; acc[3]  += q0.w * kv;
            acc[4]  += q1.x * kv; acc[5]  += q1.y * kv; acc[6]  += q1.z * kv; acc[7]  += q1.w * kv;
            acc[8]  += q2.x * kv; acc[9]  += q2.y * kv; acc[10] += q2.z * kv; acc[11] += q2.w * kv;
            acc[12] += q3.x * kv; acc[13] += q3.y * kv; acc[14] += q3.z * kv; acc[15] += q3.w * kv;
        }
#pragma unroll
        for (int j = 0; j < 16; j++) {
            int n = ng * 16 + j;
            int rp = ((n >> 3) - (m >> 3) + 7) * 15 + ((n & 7) - (m & 7) + 7);
            ASP[n * 64 + m] = acc[j] + BT[rp];
        }
    }
    __syncthreads();

    // ---- phase 6: softmax over ASP rows (4 threads per row) ----
    {
        int r  = t >> 2;
        int l4 = t & 3;
        float* rp = &ASP[r * 64 + l4 * 16];
        float4 v[4];
#pragma unroll
        for (int g = 0; g < 4; g++) v[g] = *(float4*)(rp + g * 4);
        float mx = -1e30f;
#pragma unroll
        for (int g = 0; g < 4; g++)
            mx = fmaxf(mx, fmaxf(fmaxf(v[g].x, v[g].y), fmaxf(v[g].z, v[g].w)));
        mx = fmaxf(mx, __shfl_xor_sync(0xffffffffu, mx, 1));
        mx = fmaxf(mx, __shfl_xor_sync(0xffffffffu, mx, 2));
        float sum = 0.f;
#pragma unroll
        for (int g = 0; g < 4; g++) {
            v[g].x = __expf(v[g].x - mx); v[g].y = __expf(v[g].y - mx);
            v[g].z = __expf(v[g].z - mx); v[g].w = __expf(v[g].w - mx);
            sum += v[g].x + v[g].y + v[g].z + v[g].w;
        }
        sum += __shfl_xor_sync(0xffffffffu, sum, 1);
        sum += __shfl_xor_sync(0xffffffffu, sum, 2);
        float inv = 1.0f / sum;
#pragma unroll
        for (int g = 0; g < 4; g++) {
            v[g].x *= inv; v[g].y *= inv; v[g].z *= inv; v[g].w *= inv;
            *(float4*)(rp + g * 4) = v[g];
        }
    }
    __syncthreads();

    // ---- phase 7: TMP = softmax(ACH) @ v  (ach softmax done in-register) ----
    {
        int c  = t >> 4;
        int nb = (t & 15) * 4;
        float a[16];
#pragma unroll
        for (int d = 0; d < 16; d++) a[d] = ACH[c * 17 + d];
        float mx = -1e30f;
#pragma unroll
        for (int d = 0; d < 16; d++) mx = fmaxf(mx, a[d]);
        float sum = 0.f;
#pragma unroll
        for (int d = 0; d < 16; d++) { a[d] = __expf(a[d] - mx); sum += a[d]; }
        float inv = 1.0f / sum;
        float4 acc = make_float4(0.f, 0.f, 0.f, 0.f);
#pragma unroll
        for (int d = 0; d < 16; d++) {
            float w = a[d] * inv;
            float4 v4 = *(float4*)&CV[(32 + d) * 68 + nb];
            acc.x += w * v4.x; acc.y += w * v4.y; acc.z += w * v4.z; acc.w += w * v4.w;
        }
        *(float4*)&TMP[c * 64 + nb] = acc;
    }
    __syncthreads();

    // ---- phase 8: out[c][m] = sum_n TMP[c][n] * ASP[n][m] -> g_mid ----
    {
        int c  = t >> 4;
        int mb = (t & 15) * 4;
        float4 acc = make_float4(0.f, 0.f, 0.f, 0.f);
#pragma unroll 8
        for (int n = 0; n < 64; n++) {
            float a = TMP[c * 64 + n];
            float4 p4 = *(float4*)&ASP[n * 64 + mb];
            acc.x += a * p4.x; acc.y += a * p4.y; acc.z += a * p4.z; acc.w += a * p4.w;
        }
        int dy = mb >> 3, dx = mb & 7;
        float* op = g_mid + (size_t)(h * 16 + c) * NP + base + (size_t)dy * 512 + dx;
        *(float4*)op = acc;
    }
}

// ---------------------------------------------------------------------------
extern "C" void kernel_launch(void* const* d_in, const int* in_sizes, int n_in,
                              void* d_out, int out_size) {
    const float* x      = (const float*)d_in[0];
    const float* qkv_w  = (const float*)d_in[1];
    const float* qkv_b  = (const float*)d_in[2];
    const float* dw_w   = (const float*)d_in[3];
    const float* dw_b   = (const float*)d_in[4];
    const float* proj_w = (const float*)d_in[5];
    const float* proj_b = (const float*)d_in[6];
    const float* temp   = (const float*)d_in[7];
    const float* btab   = (const float*)d_in[8];
    float* out = (float*)d_out;

    static bool attr_set = false;
    if (!attr_set) {
        cudaFuncSetAttribute(window_attn_fused,
                             cudaFuncAttributeMaxDynamicSharedMemorySize, SMEM_BYTES);
        attr_set = true;
    }

    dim3 g2(6, 4096);
    window_attn_fused<<<g2, 256, SMEM_BYTES>>>(x, qkv_w, qkv_b, dw_w, dw_b, temp, btab);

    dim3 g3(2048, 1);
    k_gemm_proj<<<g3, 256>>>(proj_w, proj_b, out);
}

// round 6
// speedup vs baseline: 1.2901x; 1.0025x over previous
#include <cuda_runtime.h>

#define NP 262144          // 512*512 pixels
#define HDIM 96

// Scratch (allowed: __device__ globals)
__device__ float g_mid[(size_t)HDIM * NP];   // attention output, pre-proj

// ---------------------------------------------------------------------------
// Proj SGEMM: C[o][p] = sum_i A[o][i] * g_mid[i][p] + bias[o]
// K = 96, BM = 96, BN = 128, 256 threads, 6x8 micro-tile.
// ---------------------------------------------------------------------------
__global__ __launch_bounds__(256) void k_gemm_proj(const float* __restrict__ A,
                                                   const float* __restrict__ bias,
                                                   float* __restrict__ C) {
    __shared__ __align__(16) float As[48][96];
    __shared__ __align__(16) float Bs[48][128];

    const int t  = threadIdx.x;
    const int tx = t & 15;
    const int ty = t >> 4;
    const size_t p0 = (size_t)blockIdx.x * 128;
    const float* __restrict__ B = g_mid;

    float acc[6][8];
#pragma unroll
    for (int m = 0; m < 6; m++) {
        float bv = bias[ty * 6 + m];
#pragma unroll
        for (int n = 0; n < 8; n++) acc[m][n] = bv;
    }

    for (int kt = 0; kt < 2; kt++) {
        for (int idx = t; idx < 48 * 96; idx += 256) {
            int o = idx / 48, k = idx % 48;
            As[k][o] = A[o * 96 + kt * 48 + k];
        }
        for (int idx = t; idx < 48 * 32; idx += 256) {
            int k = idx >> 5, c4 = idx & 31;
            *(float4*)&Bs[k][c4 * 4] =
                *(const float4*)(B + (size_t)(kt * 48 + k) * NP + p0 + c4 * 4);
        }
        __syncthreads();

#pragma unroll 4
        for (int k = 0; k < 48; k++) {
            float a[6];
#pragma unroll
            for (int m = 0; m < 6; m++) a[m] = As[k][ty * 6 + m];
            float4 b0 = *(float4*)&Bs[k][tx * 4];
            float4 b1 = *(float4*)&Bs[k][64 + tx * 4];
            float bb[8] = {b0.x, b0.y, b0.z, b0.w, b1.x, b1.y, b1.z, b1.w};
#pragma unroll
            for (int m = 0; m < 6; m++)
#pragma unroll
                for (int n = 0; n < 8; n++) acc[m][n] += a[m] * bb[n];
        }
        __syncthreads();
    }

#pragma unroll
    for (int m = 0; m < 6; m++) {
        float* cp = C + (size_t)(ty * 6 + m) * NP + p0;
        *(float4*)(cp + tx * 4)      = make_float4(acc[m][0], acc[m][1], acc[m][2], acc[m][3]);
        *(float4*)(cp + 64 + tx * 4) = make_float4(acc[m][4], acc[m][5], acc[m][6], acc[m][7]);
    }
}

// ---------------------------------------------------------------------------
// Fused per-(head, window) kernel, 256 threads:
//   qkv 1x1 GEMM (48x96 . 96x64) -> depthwise 3x3 (SAME in window) ->
//   L2-normalize q/k over spatial -> channel attn (16x16, *temp) +
//   spatial attn (64x64 + rel bias) -> softmax -> attn_ch @ v @ attn_sp
// Dynamic smem 71424 B, unioned regions. grid = (6 heads, 4096 windows).
// ---------------------------------------------------------------------------
// smem offsets (floats)
#define OFF_XS   0        // [96][64]             (dead after GEMM)
#define OFF_W    6144     // [48][97]             (dead after GEMM)
#define OFF_ASP  0        // [64][64]   overlays XS
#define OFF_TMP  4096     // [16][64]   overlays XS
#define OFF_ACH  5120     // [16][17]   overlays XS tail
#define OFF_RAW  10800    // [48][64]
#define OFF_CV   13872    // [48][68]   (padded stride 68)
#define OFF_DWW  17136    // [48][9]
#define OFF_DWB  17568    // [48]
#define OFF_BT   17616    // [225]
#define SMEM_FLOATS 17856
#define SMEM_BYTES  (SMEM_FLOATS * 4)

__global__ __launch_bounds__(256) void window_attn_fused(
        const float* __restrict__ x,
        const float* __restrict__ qkv_w,
        const float* __restrict__ qkv_b,
        const float* __restrict__ dw_w,
        const float* __restrict__ dw_b,
        const float* __restrict__ temperature,
        const float* __restrict__ bias_table) {
    extern __shared__ __align__(16) float sm[];
    float* XS  = sm + OFF_XS;
    float* Wt  = sm + OFF_W;
    float* ASP = sm + OFF_ASP;
    float* TMP = sm + OFF_TMP;
    float* ACH = sm + OFF_ACH;
    float* RAW = sm + OFF_RAW;
    float* CV  = sm + OFF_CV;
    float* DWW = sm + OFF_DWW;
    float* DWB = sm + OFF_DWB;
    float* BT  = sm + OFF_BT;

    const int t   = threadIdx.x;
    const int h   = blockIdx.x;      // 0..5
    const int win = blockIdx.y;      // 0..4095
    const int wy  = win >> 6, wx = win & 63;
    const size_t base = (size_t)(wy * 8) * 512 + (size_t)wx * 8;

    // ---- phase 0: loads ----
    // x window: 96 channels x 64 px (float4)
    for (int i = t; i < 1536; i += 256) {
        int ch = i >> 4, r = i & 15;
        int dy = r >> 1, half = r & 1;
        *(float4*)&XS[ch * 64 + dy * 8 + half * 4] =
            *(const float4*)(x + (size_t)ch * NP + base + (size_t)dy * 512 + half * 4);
    }
    // qkv weights for this head's 48 output channels (padded stride 97)
    for (int i = t; i < 1152; i += 256) {
        int row = i / 24, c4 = i % 24;
        int gch = (row >> 4) * 96 + h * 16 + (row & 15);
        float4 wv = *(const float4*)(qkv_w + gch * 96 + c4 * 4);
        float* d = &Wt[row * 97 + c4 * 4];
        d[0] = wv.x; d[1] = wv.y; d[2] = wv.z; d[3] = wv.w;
    }
    // depthwise weights / bias / bias table column
    for (int i = t; i < 432; i += 256) {
        int cl = i / 9, j = i % 9;
        int gch = (cl >> 4) * 96 + h * 16 + (cl & 15);
        DWW[cl * 9 + j] = dw_w[gch * 9 + j];
    }
    if (t < 48) {
        int gch = (t >> 4) * 96 + h * 16 + (t & 15);
        DWB[t] = dw_b[gch];
    }
    // FIX: full coverage of the 225-entry bias table (previous conditional
    // left BT[208..224] uninitialized -> rel_err 2.2e-2)
    for (int i = t; i < 225; i += 256) BT[i] = bias_table[i * 6 + h];
    __syncthreads();

    // ---- phase 1: qkv GEMM -> RAW[48][64] (+bias) ----
    {
        const int r0 = t >> 4;       // 0..15
        const int tx = t & 15;       // 4 cols each
        float a0r[4], a1r[4], a2r[4];
        float b0 = qkv_b[0 * 96 + h * 16 + r0];
        float b1 = qkv_b[1 * 96 + h * 16 + r0];
        float b2 = qkv_b[2 * 96 + h * 16 + r0];
#pragma unroll
        for (int j = 0; j < 4; j++) { a0r[j] = b0; a1r[j] = b1; a2r[j] = b2; }
#pragma unroll 4
        for (int k = 0; k < 96; k++) {
            float4 bx = *(float4*)&XS[k * 64 + tx * 4];
            float a0 = Wt[r0 * 97 + k];
            float a1 = Wt[(r0 + 16) * 97 + k];
            float a2 = Wt[(r0 + 32) * 97 + k];
            a0r[0] += a0 * bx.x; a0r[1] += a0 * bx.y; a0r[2] += a0 * bx.z; a0r[3] += a0 * bx.w;
            a1r[0] += a1 * bx.x; a1r[1] += a1 * bx.y; a1r[2] += a1 * bx.z; a1r[3] += a1 * bx.w;
            a2r[0] += a2 * bx.x; a2r[1] += a2 * bx.y; a2r[2] += a2 * bx.z; a2r[3] += a2 * bx.w;
        }
        *(float4*)&RAW[r0 * 64 + tx * 4]        = make_float4(a0r[0], a0r[1], a0r[2], a0r[3]);
        *(float4*)&RAW[(r0 + 16) * 64 + tx * 4] = make_float4(a1r[0], a1r[1], a1r[2], a1r[3]);
        *(float4*)&RAW[(r0 + 32) * 64 + tx * 4] = make_float4(a2r[0], a2r[1], a2r[2], a2r[3]);
    }
    __syncthreads();

    // ---- phase 2: depthwise 3x3 (zero pad at window border) -> CV ----
    for (int i = t; i < 3072; i += 256) {
        int cl = i >> 6, pos = i & 63;
        int dy = pos >> 3, dx = pos & 7;
        float acc = DWB[cl];
#pragma unroll
        for (int ky = 0; ky < 3; ky++) {
            int yy = dy + ky - 1;
            if (yy < 0 || yy >= 8) continue;
#pragma unroll
            for (int kx = 0; kx < 3; kx++) {
                int xx = dx + kx - 1;
                if (xx < 0 || xx >= 8) continue;
                acc += DWW[cl * 9 + ky * 3 + kx] * RAW[cl * 64 + yy * 8 + xx];
            }
        }
        CV[cl * 68 + pos] = acc;
    }
    __syncthreads();

    // ---- phase 3: L2-normalize q rows (0-15) and k rows (16-31) over N=64 ----
    {
        int r  = t >> 3;             // 0..31
        int l8 = t & 7;              // 8 elems each
        float* rp = &CV[r * 68 + l8 * 8];
        float4 v0 = *(float4*)rp;
        float4 v1 = *(float4*)(rp + 4);
        float s = v0.x*v0.x + v0.y*v0.y + v0.z*v0.z + v0.w*v0.w
                + v1.x*v1.x + v1.y*v1.y + v1.z*v1.z + v1.w*v1.w;
        s += __shfl_xor_sync(0xffffffffu, s, 1);
        s += __shfl_xor_sync(0xffffffffu, s, 2);
        s += __shfl_xor_sync(0xffffffffu, s, 4);
        float nf = 1.0f / fmaxf(sqrtf(s), 1e-12f);
        v0.x *= nf; v0.y *= nf; v0.z *= nf; v0.w *= nf;
        v1.x *= nf; v1.y *= nf; v1.z *= nf; v1.w *= nf;
        *(float4*)rp       = v0;
        *(float4*)(rp + 4) = v1;
    }
    __syncthreads();

    const float tempv = temperature[h];

    // ---- phase 4: channel attention logits ACH[c][d] (stride 17) ----
    {
        int c = t >> 4, d = t & 15;
        float s = 0.f;
#pragma unroll
        for (int n4 = 0; n4 < 16; n4++) {
            float4 q4 = *(float4*)&CV[c * 68 + n4 * 4];
            float4 k4 = *(float4*)&CV[(16 + d) * 68 + n4 * 4];
            s += q4.x * k4.x + q4.y * k4.y + q4.z * k4.z + q4.w * k4.w;
        }
        ACH[c * 17 + d] = s * tempv;
    }

    // ---- phase 5: spatial attention logits + rel bias -> ASP[n][m] ----
    {
        int m  = t & 63;
        int ng = t >> 6;             // n block of 16
        float kb[16];
#pragma unroll
        for (int c = 0; c < 16; c++) kb[c] = CV[(16 + c) * 68 + m];
        float acc[16];
#pragma unroll
        for (int j = 0; j < 16; j++) acc[j] = 0.f;
#pragma unroll
        for (int c = 0; c < 16; c++) {
            float kv = kb[c];
            float4 q0 = *(float4*)&CV[c * 68 + ng * 16];
            float4 q1 = *(float4*)&CV[c * 68 + ng * 16 + 4];
            float4 q2 = *(float4*)&CV[c * 68 + ng * 16 + 8];
            float4 q3 = *(float4*)&CV[c * 68 + ng * 16 + 12];
            acc[0]  += q0.x * kv; acc[1]  += q0.y * kv; acc[2]  += q0.z * kv; acc[3]  += q0.w * kv;
            acc[4]  += q1.x * kv; acc[5]  += q1.y * kv; acc[6]  += q1.z * kv; acc[7]  += q1.w * kv;
            acc[8]  += q2.x * kv; acc[9]  += q2.y * kv; acc[10] += q2.z * kv; acc[11] += q2.w * kv;
            acc[12] += q3.x * kv; acc[13] += q3.y * kv; acc[14] += q3.z * kv; acc[15] += q3.w * kv;
        }
#pragma unroll
        for (int j = 0; j < 16; j++) {
            int n = ng * 16 + j;
            int rp = ((n >> 3) - (m >> 3) + 7) * 15 + ((n & 7) - (m & 7) + 7);
            ASP[n * 64 + m] = acc[j] + BT[rp];
        }
    }
    __syncthreads();

    // ---- phase 6: softmax over ASP rows (4 threads per row) ----
    {
        int r  = t >> 2;
        int l4 = t & 3;
        float* rp = &ASP[r * 64 + l4 * 16];
        float4 v[4];
#pragma unroll
        for (int g = 0; g < 4; g++) v[g] = *(float4*)(rp + g * 4);
        float mx = -1e30f;
#pragma unroll
        for (int g = 0; g < 4; g++)
            mx = fmaxf(mx, fmaxf(fmaxf(v[g].x, v[g].y), fmaxf(v[g].z, v[g].w)));
        mx = fmaxf(mx, __shfl_xor_sync(0xffffffffu, mx, 1));
        mx = fmaxf(mx, __shfl_xor_sync(0xffffffffu, mx, 2));
        float sum = 0.f;
#pragma unroll
        for (int g = 0; g < 4; g++) {
            v[g].x = __expf(v[g].x - mx); v[g].y = __expf(v[g].y - mx);
            v[g].z = __expf(v[g].z - mx); v[g].w = __expf(v[g].w - mx);
            sum += v[g].x + v[g].y + v[g].z + v[g].w;
        }
        sum += __shfl_xor_sync(0xffffffffu, sum, 1);
        sum += __shfl_xor_sync(0xffffffffu, sum, 2);
        float inv = 1.0f / sum;
#pragma unroll
        for (int g = 0; g < 4; g++) {
            v[g].x *= inv; v[g].y *= inv; v[g].z *= inv; v[g].w *= inv;
            *(float4*)(rp + g * 4) = v[g];
        }
    }
    __syncthreads();

    // ---- phase 7: TMP = softmax(ACH) @ v  (ach softmax done in-register) ----
    {
        int c  = t >> 4;
        int nb = (t & 15) * 4;
        float a[16];
#pragma unroll
        for (int d = 0; d < 16; d++) a[d] = ACH[c * 17 + d];
        float mx = -1e30f;
#pragma unroll
        for (int d = 0; d < 16; d++) mx = fmaxf(mx, a[d]);
        float sum = 0.f;
#pragma unroll
        for (int d = 0; d < 16; d++) { a[d] = __expf(a[d] - mx); sum += a[d]; }
        float inv = 1.0f / sum;
        float4 acc = make_float4(0.f, 0.f, 0.f, 0.f);
#pragma unroll
        for (int d = 0; d < 16; d++) {
            float w = a[d] * inv;
            float4 v4 = *(float4*)&CV[(32 + d) * 68 + nb];
            acc.x += w * v4.x; acc.y += w * v4.y; acc.z += w * v4.z; acc.w += w * v4.w;
        }
        *(float4*)&TMP[c * 64 + nb] = acc;
    }
    __syncthreads();

    // ---- phase 8: out[c][m] = sum_n TMP[c][n] * ASP[n][m] -> g_mid ----
    {
        int c  = t >> 4;
        int mb = (t & 15) * 4;
        float4 acc = make_float4(0.f, 0.f, 0.f, 0.f);
#pragma unroll 8
        for (int n = 0; n < 64; n++) {
            float a = TMP[c * 64 + n];
            float4 p4 = *(float4*)&ASP[n * 64 + mb];
            acc.x += a * p4.x; acc.y += a * p4.y; acc.z += a * p4.z; acc.w += a * p4.w;
        }
        int dy = mb >> 3, dx = mb & 7;
        float* op = g_mid + (size_t)(h * 16 + c) * NP + base + (size_t)dy * 512 + dx;
        *(float4*)op = acc;
    }
}

// ---------------------------------------------------------------------------
extern "C" void kernel_launch(void* const* d_in, const int* in_sizes, int n_in,
                              void* d_out, int out_size) {
    const float* x      = (const float*)d_in[0];
    const float* qkv_w  = (const float*)d_in[1];
    const float* qkv_b  = (const float*)d_in[2];
    const float* dw_w   = (const float*)d_in[3];
    const float* dw_b   = (const float*)d_in[4];
    const float* proj_w = (const float*)d_in[5];
    const float* proj_b = (const float*)d_in[6];
    const float* temp   = (const float*)d_in[7];
    const float* btab   = (const float*)d_in[8];
    float* out = (float*)d_out;

    static bool attr_set = false;
    if (!attr_set) {
        cudaFuncSetAttribute(window_attn_fused,
                             cudaFuncAttributeMaxDynamicSharedMemorySize, SMEM_BYTES);
        attr_set = true;
    }

    dim3 g2(6, 4096);
    window_attn_fused<<<g2, 256, SMEM_BYTES>>>(x, qkv_w, qkv_b, dw_w, dw_b, temp, btab);

    dim3 g3(2048, 1);
    k_gemm_proj<<<g3, 256>>>(proj_w, proj_b, out);
}

// round 7
// speedup vs baseline: 1.2914x; 1.0010x over previous
#include <cuda_runtime.h>

#define NP 262144          // 512*512 pixels
#define HDIM 96

// Scratch (allowed: __device__ globals)
__device__ float g_mid[(size_t)HDIM * NP];   // attention output, pre-proj

// ---------------------------------------------------------------------------
// Proj SGEMM: C[o][p] = sum_i A[o][i] * g_mid[i][p] + bias[o]
// K = 96, BM = 96, BN = 128, 256 threads, 6x8 micro-tile.
// ---------------------------------------------------------------------------
__global__ __launch_bounds__(256) void k_gemm_proj(const float* __restrict__ A,
                                                   const float* __restrict__ bias,
                                                   float* __restrict__ C) {
    __shared__ __align__(16) float As[48][96];
    __shared__ __align__(16) float Bs[48][128];

    const int t  = threadIdx.x;
    const int tx = t & 15;
    const int ty = t >> 4;
    const size_t p0 = (size_t)blockIdx.x * 128;
    const float* __restrict__ B = g_mid;

    float acc[6][8];
#pragma unroll
    for (int m = 0; m < 6; m++) {
        float bv = bias[ty * 6 + m];
#pragma unroll
        for (int n = 0; n < 8; n++) acc[m][n] = bv;
    }

    for (int kt = 0; kt < 2; kt++) {
        for (int idx = t; idx < 48 * 96; idx += 256) {
            int o = idx / 48, k = idx % 48;
            As[k][o] = A[o * 96 + kt * 48 + k];
        }
        for (int idx = t; idx < 48 * 32; idx += 256) {
            int k = idx >> 5, c4 = idx & 31;
            *(float4*)&Bs[k][c4 * 4] =
                *(const float4*)(B + (size_t)(kt * 48 + k) * NP + p0 + c4 * 4);
        }
        __syncthreads();

#pragma unroll 4
        for (int k = 0; k < 48; k++) {
            float a[6];
#pragma unroll
            for (int m = 0; m < 6; m++) a[m] = As[k][ty * 6 + m];
            float4 b0 = *(float4*)&Bs[k][tx * 4];
            float4 b1 = *(float4*)&Bs[k][64 + tx * 4];
            float bb[8] = {b0.x, b0.y, b0.z, b0.w, b1.x, b1.y, b1.z, b1.w};
#pragma unroll
            for (int m = 0; m < 6; m++)
#pragma unroll
                for (int n = 0; n < 8; n++) acc[m][n] += a[m] * bb[n];
        }
        __syncthreads();
    }

#pragma unroll
    for (int m = 0; m < 6; m++) {
        float* cp = C + (size_t)(ty * 6 + m) * NP + p0;
        *(float4*)(cp + tx * 4)      = make_float4(acc[m][0], acc[m][1], acc[m][2], acc[m][3]);
        *(float4*)(cp + 64 + tx * 4) = make_float4(acc[m][4], acc[m][5], acc[m][6], acc[m][7]);
    }
}

// ---------------------------------------------------------------------------
// Fused per-(head, window) kernel, 256 threads:
//   qkv 1x1 GEMM (48x96 . 96x64) -> depthwise 3x3 (SAME in window) ->
//   L2-normalize q/k over spatial -> channel attn (16x16, *temp) +
//   spatial attn (64x64 + rel bias) -> softmax -> attn_ch @ v @ attn_sp
// Dynamic smem 71424 B, unioned regions. grid = (6 heads, 4096 windows).
// ---------------------------------------------------------------------------
// smem offsets (floats)
#define OFF_XS   0        // [96][64]             (dead after GEMM)
#define OFF_W    6144     // [48][97]             (dead after GEMM)
#define OFF_ASP  0        // [64][64]   overlays XS
#define OFF_TMP  4096     // [16][64]   overlays XS
#define OFF_ACH  5120     // [16][17]   overlays XS tail
#define OFF_RAW  10800    // [48][64]
#define OFF_CV   13872    // [48][68]   (padded stride 68)
#define OFF_DWW  17136    // [48][9]
#define OFF_DWB  17568    // [48]
#define OFF_BT   17616    // [225]
#define SMEM_FLOATS 17856
#define SMEM_BYTES  (SMEM_FLOATS * 4)

__global__ __launch_bounds__(256) void window_attn_fused(
        const float* __restrict__ x,
        const float* __restrict__ qkv_w,
        const float* __restrict__ qkv_b,
        const float* __restrict__ dw_w,
        const float* __restrict__ dw_b,
        const float* __restrict__ temperature,
        const float* __restrict__ bias_table) {
    extern __shared__ __align__(16) float sm[];
    float* XS  = sm + OFF_XS;
    float* Wt  = sm + OFF_W;
    float* ASP = sm + OFF_ASP;
    float* TMP = sm + OFF_TMP;
    float* ACH = sm + OFF_ACH;
    float* RAW = sm + OFF_RAW;
    float* CV  = sm + OFF_CV;
    float* DWW = sm + OFF_DWW;
    float* DWB = sm + OFF_DWB;
    float* BT  = sm + OFF_BT;

    const int t   = threadIdx.x;
    const int h   = blockIdx.x;      // 0..5
    const int win = blockIdx.y;      // 0..4095
    const int wy  = win >> 6, wx = win & 63;
    const size_t base = (size_t)(wy * 8) * 512 + (size_t)wx * 8;

    // ---- phase 0: loads ----
    // x window: 96 channels x 64 px (float4)
    for (int i = t; i < 1536; i += 256) {
        int ch = i >> 4, r = i & 15;
        int dy = r >> 1, half = r & 1;
        *(float4*)&XS[ch * 64 + dy * 8 + half * 4] =
            *(const float4*)(x + (size_t)ch * NP + base + (size_t)dy * 512 + half * 4);
    }
    // qkv weights for this head's 48 output channels (padded stride 97)
    for (int i = t; i < 1152; i += 256) {
        int row = i / 24, c4 = i % 24;
        int gch = (row >> 4) * 96 + h * 16 + (row & 15);
        float4 wv = *(const float4*)(qkv_w + gch * 96 + c4 * 4);
        float* d = &Wt[row * 97 + c4 * 4];
        d[0] = wv.x; d[1] = wv.y; d[2] = wv.z; d[3] = wv.w;
    }
    // depthwise weights / bias / bias table column
    for (int i = t; i < 432; i += 256) {
        int cl = i / 9, j = i % 9;
        int gch = (cl >> 4) * 96 + h * 16 + (cl & 15);
        DWW[cl * 9 + j] = dw_w[gch * 9 + j];
    }
    if (t < 48) {
        int gch = (t >> 4) * 96 + h * 16 + (t & 15);
        DWB[t] = dw_b[gch];
    }
    // FIX: full coverage of the 225-entry bias table (previous conditional
    // left BT[208..224] uninitialized -> rel_err 2.2e-2)
    for (int i = t; i < 225; i += 256) BT[i] = bias_table[i * 6 + h];
    __syncthreads();

    // ---- phase 1: qkv GEMM -> RAW[48][64] (+bias) ----
    {
        const int r0 = t >> 4;       // 0..15
        const int tx = t & 15;       // 4 cols each
        float a0r[4], a1r[4], a2r[4];
        float b0 = qkv_b[0 * 96 + h * 16 + r0];
        float b1 = qkv_b[1 * 96 + h * 16 + r0];
        float b2 = qkv_b[2 * 96 + h * 16 + r0];
#pragma unroll
        for (int j = 0; j < 4; j++) { a0r[j] = b0; a1r[j] = b1; a2r[j] = b2; }
#pragma unroll 4
        for (int k = 0; k < 96; k++) {
            float4 bx = *(float4*)&XS[k * 64 + tx * 4];
            float a0 = Wt[r0 * 97 + k];
            float a1 = Wt[(r0 + 16) * 97 + k];
            float a2 = Wt[(r0 + 32) * 97 + k];
            a0r[0] += a0 * bx.x; a0r[1] += a0 * bx.y; a0r[2] += a0 * bx.z; a0r[3] += a0 * bx.w;
            a1r[0] += a1 * bx.x; a1r[1] += a1 * bx.y; a1r[2] += a1 * bx.z; a1r[3] += a1 * bx.w;
            a2r[0] += a2 * bx.x; a2r[1] += a2 * bx.y; a2r[2] += a2 * bx.z; a2r[3] += a2 * bx.w;
        }
        *(float4*)&RAW[r0 * 64 + tx * 4]        = make_float4(a0r[0], a0r[1], a0r[2], a0r[3]);
        *(float4*)&RAW[(r0 + 16) * 64 + tx * 4] = make_float4(a1r[0], a1r[1], a1r[2], a1r[3]);
        *(float4*)&RAW[(r0 + 32) * 64 + tx * 4] = make_float4(a2r[0], a2r[1], a2r[2], a2r[3]);
    }
    __syncthreads();

    // ---- phase 2: depthwise 3x3 (zero pad at window border) -> CV ----
    for (int i = t; i < 3072; i += 256) {
        int cl = i >> 6, pos = i & 63;
        int dy = pos >> 3, dx = pos & 7;
        float acc = DWB[cl];
#pragma unroll
        for (int ky = 0; ky < 3; ky++) {
            int yy = dy + ky - 1;
            if (yy < 0 || yy >= 8) continue;
#pragma unroll
            for (int kx = 0; kx < 3; kx++) {
                int xx = dx + kx - 1;
                if (xx < 0 || xx >= 8) continue;
                acc += DWW[cl * 9 + ky * 3 + kx] * RAW[cl * 64 + yy * 8 + xx];
            }
        }
        CV[cl * 68 + pos] = acc;
    }
    __syncthreads();

    // ---- phase 3: L2-normalize q rows (0-15) and k rows (16-31) over N=64 ----
    {
        int r  = t >> 3;             // 0..31
        int l8 = t & 7;              // 8 elems each
        float* rp = &CV[r * 68 + l8 * 8];
        float4 v0 = *(float4*)rp;
        float4 v1 = *(float4*)(rp + 4);
        float s = v0.x*v0.x + v0.y*v0.y + v0.z*v0.z + v0.w*v0.w
                + v1.x*v1.x + v1.y*v1.y + v1.z*v1.z + v1.w*v1.w;
        s += __shfl_xor_sync(0xffffffffu, s, 1);
        s += __shfl_xor_sync(0xffffffffu, s, 2);
        s += __shfl_xor_sync(0xffffffffu, s, 4);
        float nf = 1.0f / fmaxf(sqrtf(s), 1e-12f);
        v0.x *= nf; v0.y *= nf; v0.z *= nf; v0.w *= nf;
        v1.x *= nf; v1.y *= nf; v1.z *= nf; v1.w *= nf;
        *(float4*)rp       = v0;
        *(float4*)(rp + 4) = v1;
    }
    __syncthreads();

    const float tempv = temperature[h];

    // ---- phase 4: channel attention logits ACH[c][d] (stride 17) ----
    {
        int c = t >> 4, d = t & 15;
        float s = 0.f;
#pragma unroll
        for (int n4 = 0; n4 < 16; n4++) {
            float4 q4 = *(float4*)&CV[c * 68 + n4 * 4];
            float4 k4 = *(float4*)&CV[(16 + d) * 68 + n4 * 4];
            s += q4.x * k4.x + q4.y * k4.y + q4.z * k4.z + q4.w * k4.w;
        }
        ACH[c * 17 + d] = s * tempv;
    }

    // ---- phase 5: spatial attention logits + rel bias -> ASP[n][m] ----
    {
        int m  = t & 63;
        int ng = t >> 6;             // n block of 16
        float kb[16];
#pragma unroll
        for (int c = 0; c < 16; c++) kb[c] = CV[(16 + c) * 68 + m];
        float acc[16];
#pragma unroll
        for (int j = 0; j < 16; j++) acc[j] = 0.f;
#pragma unroll
        for (int c = 0; c < 16; c++) {
            float kv = kb[c];
            float4 q0 = *(float4*)&CV[c * 68 + ng * 16];
            float4 q1 = *(float4*)&CV[c * 68 + ng * 16 + 4];
            float4 q2 = *(float4*)&CV[c * 68 + ng * 16 + 8];
            float4 q3 = *(float4*)&CV[c * 68 + ng * 16 + 12];
            acc[0]  += q0.x * kv; acc[1]  += q0.y * kv; acc[2]  += q0.z * kv; acc[3]  += q0.w * kv;
            acc[4]  += q1.x * kv; acc[5]  += q1.y * kv; acc[6]  += q1.z * kv; acc[7]  += q1.w * kv;
            acc[8]  += q2.x * kv; acc[9]  += q2.y * kv; acc[10] += q2.z * kv; acc[11] += q2.w * kv;
            acc[12] += q3.x * kv; acc[13] += q3.y * kv; acc[14] += q3.z * kv; acc[15] += q3.w * kv;
        }
#pragma unroll
        for (int j = 0; j < 16; j++) {
            int n = ng * 16 + j;
            int rp = ((n >> 3) - (m >> 3) + 7) * 15 + ((n & 7) - (m & 7) + 7);
            ASP[n * 64 + m] = acc[j] + BT[rp];
        }
    }
    __syncthreads();

    // ---- phase 6: softmax over ASP rows (4 threads per row) ----
    {
        int r  = t >> 2;
        int l4 = t & 3;
        float* rp = &ASP[r * 64 + l4 * 16];
        float4 v[4];
#pragma unroll
        for (int g = 0; g < 4; g++) v[g] = *(float4*)(rp + g * 4);
        float mx = -1e30f;
#pragma unroll
        for (int g = 0; g < 4; g++)
            mx = fmaxf(mx, fmaxf(fmaxf(v[g].x, v[g].y), fmaxf(v[g].z, v[g].w)));
        mx = fmaxf(mx, __shfl_xor_sync(0xffffffffu, mx, 1));
        mx = fmaxf(mx, __shfl_xor_sync(0xffffffffu, mx, 2));
        float sum = 0.f;
#pragma unroll
        for (int g = 0; g < 4; g++) {
            v[g].x = __expf(v[g].x - mx); v[g].y = __expf(v[g].y - mx);
            v[g].z = __expf(v[g].z - mx); v[g].w = __expf(v[g].w - mx);
            sum += v[g].x + v[g].y + v[g].z + v[g].w;
        }
        sum += __shfl_xor_sync(0xffffffffu, sum, 1);
        sum += __shfl_xor_sync(0xffffffffu, sum, 2);
        float inv = 1.0f / sum;
#pragma unroll
        for (int g = 0; g < 4; g++) {
            v[g].x *= inv; v[g].y *= inv; v[g].z *= inv; v[g].w *= inv;
            *(float4*)(rp + g * 4) = v[g];
        }
    }
    __syncthreads();

    // ---- phase 7: TMP = softmax(ACH) @ v  (ach softmax done in-register) ----
    {
        int c  = t >> 4;
        int nb = (t & 15) * 4;
        float a[16];
#pragma unroll
        for (int d = 0; d < 16; d++) a[d] = ACH[c * 17 + d];
        float mx = -1e30f;
#pragma unroll
        for (int d = 0; d < 16; d++) mx = fmaxf(mx, a[d]);
        float sum = 0.f;
#pragma unroll
        for (int d = 0; d < 16; d++) { a[d] = __expf(a[d] - mx); sum += a[d]; }
        float inv = 1.0f / sum;
        float4 acc = make_float4(0.f, 0.f, 0.f, 0.f);
#pragma unroll
        for (int d = 0; d < 16; d++) {
            float w = a[d] * inv;
            float4 v4 = *(float4*)&CV[(32 + d) * 68 + nb];
            acc.x += w * v4.x; acc.y += w * v4.y; acc.z += w * v4.z; acc.w += w * v4.w;
        }
        *(float4*)&TMP[c * 64 + nb] = acc;
    }
    __syncthreads();

    // ---- phase 8: out[c][m] = sum_n TMP[c][n] * ASP[n][m] -> g_mid ----
    {
        int c  = t >> 4;
        int mb = (t & 15) * 4;
        float4 acc = make_float4(0.f, 0.f, 0.f, 0.f);
#pragma unroll 8
        for (int n = 0; n < 64; n++) {
            float a = TMP[c * 64 + n];
            float4 p4 = *(float4*)&ASP[n * 64 + mb];
            acc.x += a * p4.x; acc.y += a * p4.y; acc.z += a * p4.z; acc.w += a * p4.w;
        }
        int dy = mb >> 3, dx = mb & 7;
        float* op = g_mid + (size_t)(h * 16 + c) * NP + base + (size_t)dy * 512 + dx;
        *(float4*)op = acc;
    }
}

// ---------------------------------------------------------------------------
extern "C" void kernel_launch(void* const* d_in, const int* in_sizes, int n_in,
                              void* d_out, int out_size) {
    const float* x      = (const float*)d_in[0];
    const float* qkv_w  = (const float*)d_in[1];
    const float* qkv_b  = (const float*)d_in[2];
    const float* dw_w   = (const float*)d_in[3];
    const float* dw_b   = (const float*)d_in[4];
    const float* proj_w = (const float*)d_in[5];
    const float* proj_b = (const float*)d_in[6];
    const float* temp   = (const float*)d_in[7];
    const float* btab   = (const float*)d_in[8];
    float* out = (float*)d_out;

    static bool attr_set = false;
    if (!attr_set) {
        cudaFuncSetAttribute(window_attn_fused,
                             cudaFuncAttributeMaxDynamicSharedMemorySize, SMEM_BYTES);
        attr_set = true;
    }

    dim3 g2(6, 4096);
    window_attn_fused<<<g2, 256, SMEM_BYTES>>>(x, qkv_w, qkv_b, dw_w, dw_b, temp, btab);

    dim3 g3(2048, 1);
    k_gemm_proj<<<g3, 256>>>(proj_w, proj_b, out);
}